// round 1
// baseline (speedup 1.0000x reference)
#include <cuda_runtime.h>
#include <math.h>

#define B_ 2
#define S_ 2048
#define D_ 1024
#define H_ 16
#define DH_ 64
#define F_ 4096
#define NTOK (B_ * S_)   // 4096

// ---------------- scratch (static device globals; no allocation) ----------------
__device__ float g_h[(size_t)NTOK * D_];        // LN output (reused for both LNs)
__device__ float g_qkv[(size_t)NTOK * 3 * D_];  // qkv projection
__device__ float g_attn[(size_t)NTOK * D_];     // attention output (pre-Wout)
__device__ float g_x1[(size_t)NTOK * D_];       // residual after attention block
__device__ float g_ffn[(size_t)NTOK * F_];      // FFN hidden

// ---------------- warp/block reduction helpers ----------------
__device__ __forceinline__ float warp_sum(float v) {
#pragma unroll
    for (int o = 16; o > 0; o >>= 1) v += __shfl_xor_sync(0xffffffffu, v, o);
    return v;
}

// ---------------- LayerNorm: one block per row (D=1024), 256 threads ----------------
__global__ void __launch_bounds__(256) ln_kernel(const float* __restrict__ in,
                                                 float* __restrict__ out,
                                                 const float* __restrict__ gamma,
                                                 const float* __restrict__ beta) {
    const int row = blockIdx.x;
    const float* x = in + (size_t)row * D_;
    float* o = out + (size_t)row * D_;
    const int tid = threadIdx.x;
    const int lane = tid & 31;
    const int wid = tid >> 5;

    float v[4];
    float s = 0.f;
#pragma unroll
    for (int i = 0; i < 4; i++) {
        v[i] = x[tid + i * 256];
        s += v[i];
    }
    __shared__ float red[8];
    s = warp_sum(s);
    if (lane == 0) red[wid] = s;
    __syncthreads();
    if (tid < 32) {
        float t = (lane < 8) ? red[lane] : 0.f;
        t = warp_sum(t);
        if (lane == 0) red[0] = t;
    }
    __syncthreads();
    const float mean = red[0] * (1.f / D_);
    __syncthreads();

    float q = 0.f;
#pragma unroll
    for (int i = 0; i < 4; i++) {
        float d = v[i] - mean;
        q += d * d;
    }
    q = warp_sum(q);
    if (lane == 0) red[wid] = q;
    __syncthreads();
    if (tid < 32) {
        float t = (lane < 8) ? red[lane] : 0.f;
        t = warp_sum(t);
        if (lane == 0) red[0] = t;
    }
    __syncthreads();
    const float stdv = sqrtf(red[0] * (1.f / D_));
    const float inv = 1.f / (stdv + 1e-6f);

#pragma unroll
    for (int i = 0; i < 4; i++) {
        int c = tid + i * 256;
        o[c] = gamma[c] * ((v[i] - mean) * inv) + beta[c];
    }
}

// ---------------- SGEMM: C[M,N] = A[M,K] * B[N,K]^T  (+epilogue) ----------------
// EPI: 0 = none, 1 = +res, 2 = +bias then GELU(exact), 3 = +bias +res
#define BM 128
#define BN 128
#define BK 16

template <int EPI>
__global__ void __launch_bounds__(256) sgemm_nt(int M, int N, int K,
                                                const float* __restrict__ A,
                                                const float* __restrict__ B,
                                                float* __restrict__ C,
                                                const float* __restrict__ bias,
                                                const float* __restrict__ res) {
    __shared__ float As[BK][BM];
    __shared__ float Bs[BK][BN];

    const int tid = threadIdx.x;
    const int tx = tid & 15;       // 0..15 -> N direction
    const int ty = tid >> 4;       // 0..15 -> M direction
    const int lr = tid >> 2;       // 0..63 load row
    const int lc = (tid & 3) * 4;  // 0,4,8,12 load k-offset

    const float* Ab = A + (size_t)(blockIdx.y * BM) * K;
    const float* Bb = B + (size_t)(blockIdx.x * BN) * K;

    float acc[8][8];
#pragma unroll
    for (int i = 0; i < 8; i++)
#pragma unroll
        for (int j = 0; j < 8; j++) acc[i][j] = 0.f;

    for (int k0 = 0; k0 < K; k0 += BK) {
#pragma unroll
        for (int i = 0; i < 2; i++) {
            int r = lr + i * 64;
            float4 a = *(const float4*)(Ab + (size_t)r * K + k0 + lc);
            As[lc + 0][r] = a.x; As[lc + 1][r] = a.y;
            As[lc + 2][r] = a.z; As[lc + 3][r] = a.w;
            float4 b = *(const float4*)(Bb + (size_t)r * K + k0 + lc);
            Bs[lc + 0][r] = b.x; Bs[lc + 1][r] = b.y;
            Bs[lc + 2][r] = b.z; Bs[lc + 3][r] = b.w;
        }
        __syncthreads();
#pragma unroll
        for (int k = 0; k < BK; k++) {
            float ar[8], br[8];
            *(float4*)(ar) = *(const float4*)(&As[k][ty * 8]);
            *(float4*)(ar + 4) = *(const float4*)(&As[k][ty * 8 + 4]);
            *(float4*)(br) = *(const float4*)(&Bs[k][tx * 8]);
            *(float4*)(br + 4) = *(const float4*)(&Bs[k][tx * 8 + 4]);
#pragma unroll
            for (int i = 0; i < 8; i++)
#pragma unroll
                for (int j = 0; j < 8; j++) acc[i][j] += ar[i] * br[j];
        }
        __syncthreads();
    }

    const int col0 = blockIdx.x * BN + tx * 8;
#pragma unroll
    for (int i = 0; i < 8; i++) {
        int row = blockIdx.y * BM + ty * 8 + i;
        float* Crow = C + (size_t)row * N + col0;
        const float* Rrow = (EPI == 1 || EPI == 3) ? res + (size_t)row * N + col0 : nullptr;
        float v[8];
#pragma unroll
        for (int j = 0; j < 8; j++) {
            float t = acc[i][j];
            if (EPI == 2 || EPI == 3) t += bias[col0 + j];
            if (EPI == 2) t = 0.5f * t * (1.f + erff(t * 0.70710678118654752f));
            if (EPI == 1 || EPI == 3) t += Rrow[j];
            v[j] = t;
        }
        *(float4*)(Crow) = *(float4*)(v);
        *(float4*)(Crow + 4) = *(float4*)(v + 4);
    }
}

// ---------------- Flash attention (fp32, causal) ----------------
// grid: (S/128, H, B), 128 threads; each thread owns one query row.
__global__ void __launch_bounds__(128) attn_kernel() {
    const int tid = threadIdx.x;
    const int q0 = blockIdx.x * 128;
    const int hh = blockIdx.y;
    const int bb = blockIdx.z;
    const int s = q0 + tid;

    __shared__ float4 Ks[64 * 16];
    __shared__ float4 Vs[64 * 16];

    float qreg[64];
    {
        const float* qrow = g_qkv + (size_t)(bb * S_ + s) * (3 * D_) + hh * DH_;
#pragma unroll
        for (int i = 0; i < 16; i++) {
            float4 t = *(const float4*)(qrow + i * 4);
            qreg[i * 4 + 0] = t.x; qreg[i * 4 + 1] = t.y;
            qreg[i * 4 + 2] = t.z; qreg[i * 4 + 3] = t.w;
        }
    }

    float acc[64];
#pragma unroll
    for (int d = 0; d < 64; d++) acc[d] = 0.f;
    float m = -INFINITY, l = 0.f;

    const int ntiles = (q0 + 128) / 64;  // causal: only tiles with k0 <= max query
    for (int t0 = 0; t0 < ntiles; t0++) {
        const int k0 = t0 * 64;
        __syncthreads();
        {
            const float* Kbase = g_qkv + (size_t)(bb * S_ + k0) * (3 * D_) + D_ + hh * DH_;
            const float* Vbase = Kbase + D_;
#pragma unroll
            for (int i = 0; i < 8; i++) {
                int f = tid + i * 128;  // 0..1023
                int r = f >> 4, c = f & 15;
                Ks[f] = *(const float4*)(Kbase + (size_t)r * (3 * D_) + c * 4);
                Vs[f] = *(const float4*)(Vbase + (size_t)r * (3 * D_) + c * 4);
            }
        }
        __syncthreads();

        for (int jc = 0; jc < 4; jc++) {
            float sc[16];
#pragma unroll
            for (int jj = 0; jj < 16; jj++) {
                const int j = jc * 16 + jj;
                float sum = 0.f;
#pragma unroll
                for (int d4 = 0; d4 < 16; d4++) {
                    float4 k4 = Ks[j * 16 + d4];
                    sum += qreg[d4 * 4 + 0] * k4.x;
                    sum += qreg[d4 * 4 + 1] * k4.y;
                    sum += qreg[d4 * 4 + 2] * k4.z;
                    sum += qreg[d4 * 4 + 3] * k4.w;
                }
                sc[jj] = (k0 + j <= s) ? sum * 0.125f : -INFINITY;
            }
            float mn = m;
#pragma unroll
            for (int jj = 0; jj < 16; jj++) mn = fmaxf(mn, sc[jj]);
            const float corr = __expf(m - mn);  // first chunk: m=-inf, mn finite -> 0
            float p[16];
            float psum = 0.f;
#pragma unroll
            for (int jj = 0; jj < 16; jj++) {
                p[jj] = __expf(sc[jj] - mn);
                psum += p[jj];
            }
            l = l * corr + psum;
            m = mn;
#pragma unroll
            for (int d = 0; d < 64; d++) acc[d] *= corr;
#pragma unroll
            for (int jj = 0; jj < 16; jj++) {
                const float pv = p[jj];
                const int j = jc * 16 + jj;
#pragma unroll
                for (int d4 = 0; d4 < 16; d4++) {
                    float4 v4 = Vs[j * 16 + d4];
                    acc[d4 * 4 + 0] += pv * v4.x;
                    acc[d4 * 4 + 1] += pv * v4.y;
                    acc[d4 * 4 + 2] += pv * v4.z;
                    acc[d4 * 4 + 3] += pv * v4.w;
                }
            }
        }
    }

    const float inv = 1.f / l;
    float* orow = g_attn + (size_t)(bb * S_ + s) * D_ + hh * DH_;
#pragma unroll
    for (int i = 0; i < 16; i++) {
        float4 o;
        o.x = acc[i * 4 + 0] * inv;
        o.y = acc[i * 4 + 1] * inv;
        o.z = acc[i * 4 + 2] * inv;
        o.w = acc[i * 4 + 3] * inv;
        *(float4*)(orow + i * 4) = o;
    }
}

// ---------------- launch ----------------
extern "C" void kernel_launch(void* const* d_in, const int* in_sizes, int n_in,
                              void* d_out, int out_size) {
    const float* x = (const float*)d_in[0];
    // d_in[1] = attention_mask (causal, ignored — baked in)
    const float* Wqkv = (const float*)d_in[2];
    const float* Wout = (const float*)d_in[3];
    const float* W1 = (const float*)d_in[4];
    const float* b1 = (const float*)d_in[5];
    const float* W2 = (const float*)d_in[6];
    const float* b2 = (const float*)d_in[7];
    const float* gamma1 = (const float*)d_in[8];
    const float* beta1 = (const float*)d_in[9];
    const float* gamma2 = (const float*)d_in[10];
    const float* beta2 = (const float*)d_in[11];
    float* out = (float*)d_out;

    float* h = nullptr;  float* qkv = nullptr; float* attn = nullptr;
    float* x1 = nullptr; float* ffn = nullptr;
    // obtain raw pointers to device globals via a tiny kernel-free trick:
    // kernels reference globals directly, but GEMMs take pointers — resolve once
    // with cudaGetSymbolAddress is NOT graph-work; it is a pure host query and
    // safe to call here (no stream ops, no allocation).
    cudaGetSymbolAddress((void**)&h, g_h);
    cudaGetSymbolAddress((void**)&qkv, g_qkv);
    cudaGetSymbolAddress((void**)&attn, g_attn);
    cudaGetSymbolAddress((void**)&x1, g_x1);
    cudaGetSymbolAddress((void**)&ffn, g_ffn);

    // 1) LN1
    ln_kernel<<<NTOK, 256>>>(x, h, gamma1, beta1);
    // 2) QKV projection: [4096,1024] x [3072,1024]^T
    sgemm_nt<0><<<dim3(3 * D_ / BN, NTOK / BM), 256>>>(NTOK, 3 * D_, D_, h, Wqkv, qkv, nullptr, nullptr);
    // 3) causal flash attention
    attn_kernel<<<dim3(S_ / 128, H_, B_), 128>>>();
    // 4) output projection + residual
    sgemm_nt<1><<<dim3(D_ / BN, NTOK / BM), 256>>>(NTOK, D_, D_, attn, Wout, x1, nullptr, x);
    // 5) LN2
    ln_kernel<<<NTOK, 256>>>(x1, h, gamma2, beta2);
    // 6) FFN1 + bias + exact GELU
    sgemm_nt<2><<<dim3(F_ / BN, NTOK / BM), 256>>>(NTOK, F_, D_, h, W1, ffn, b1, nullptr);
    // 7) FFN2 + bias + residual -> out
    sgemm_nt<3><<<dim3(D_ / BN, NTOK / BM), 256>>>(NTOK, D_, F_, ffn, W2, out, b2, x1);
}

// round 6
// speedup vs baseline: 1.8057x; 1.8057x over previous
#include <cuda_runtime.h>
#include <cuda_bf16.h>
#include <math.h>
#include <stdint.h>

#define B_ 2
#define S_ 2048
#define D_ 1024
#define H_ 16
#define DH_ 64
#define F_ 4096
#define NTOK (B_ * S_)   // 4096

// ---------------- scratch (static device globals; no allocation) ----------------
__device__ float g_h[(size_t)NTOK * D_];
__device__ float g_qkv[(size_t)NTOK * 3 * D_];
__device__ float g_attn[(size_t)NTOK * D_];
__device__ float g_x1[(size_t)NTOK * D_];
__device__ float g_ffn[(size_t)NTOK * F_];

__device__ __forceinline__ uint32_t smem_u32(const void* p) {
    uint32_t a;
    asm("{ .reg .u64 t; cvta.to.shared.u64 t, %1; cvt.u32.u64 %0, t; }" : "=r"(a) : "l"(p));
    return a;
}

// ---------------- warp/block reduction helpers ----------------
__device__ __forceinline__ float warp_sum(float v) {
#pragma unroll
    for (int o = 16; o > 0; o >>= 1) v += __shfl_xor_sync(0xffffffffu, v, o);
    return v;
}

// ---------------- LayerNorm ----------------
__global__ void __launch_bounds__(256) ln_kernel(const float* __restrict__ in,
                                                 float* __restrict__ out,
                                                 const float* __restrict__ gamma,
                                                 const float* __restrict__ beta) {
    const int row = blockIdx.x;
    const float* x = in + (size_t)row * D_;
    float* o = out + (size_t)row * D_;
    const int tid = threadIdx.x;
    const int lane = tid & 31;
    const int wid = tid >> 5;

    float v[4];
    float s = 0.f;
#pragma unroll
    for (int i = 0; i < 4; i++) { v[i] = x[tid + i * 256]; s += v[i]; }
    __shared__ float red[8];
    s = warp_sum(s);
    if (lane == 0) red[wid] = s;
    __syncthreads();
    if (tid < 32) {
        float t = (lane < 8) ? red[lane] : 0.f;
        t = warp_sum(t);
        if (lane == 0) red[0] = t;
    }
    __syncthreads();
    const float mean = red[0] * (1.f / D_);
    __syncthreads();

    float q = 0.f;
#pragma unroll
    for (int i = 0; i < 4; i++) { float d = v[i] - mean; q += d * d; }
    q = warp_sum(q);
    if (lane == 0) red[wid] = q;
    __syncthreads();
    if (tid < 32) {
        float t = (lane < 8) ? red[lane] : 0.f;
        t = warp_sum(t);
        if (lane == 0) red[0] = t;
    }
    __syncthreads();
    const float stdv = sqrtf(red[0] * (1.f / D_));
    const float inv = 1.f / (stdv + 1e-6f);

#pragma unroll
    for (int i = 0; i < 4; i++) {
        int c = tid + i * 256;
        o[c] = gamma[c] * ((v[i] - mean) * inv) + beta[c];
    }
}

// ============================================================================
// bf16x3 mma.sync GEMM: C[M,N] = A[M,K] * B[N,K]^T (+epilogue)
// EPI: 0 none, 1 +res, 2 +bias+GELU, 3 +bias+res
// CTA 128x128, 8 warps (2m x 4n), warp tile 64x32, K-chunk 32, double buffered.
// Both A and B tiles stored [row, k] row-major (80B padded rows) -> plain
// ldmatrix (non-trans) yields the row.col mma fragments for BOTH operands.
// ============================================================================
#define ROWB 80
#define TILEB (128 * ROWB)
#define OFF_ALO (TILEB)
#define OFF_BHI (2 * TILEB)
#define OFF_BLO (3 * TILEB)
#define STAGE_BYTES (4 * TILEB)
#define GEMM_SMEM (2 * STAGE_BYTES)   // 81920

#define LDSM4(r, addr) \
    asm volatile("ldmatrix.sync.aligned.m8n8.x4.shared.b16 {%0,%1,%2,%3}, [%4];" \
                 : "=r"((r)[0]), "=r"((r)[1]), "=r"((r)[2]), "=r"((r)[3]) : "r"(addr))
#define MMA_BF16(c, a, b) \
    asm volatile("mma.sync.aligned.m16n8k16.row.col.f32.bf16.bf16.f32 " \
                 "{%0,%1,%2,%3}, {%4,%5,%6,%7}, {%8,%9}, {%0,%1,%2,%3};" \
                 : "+f"((c)[0]), "+f"((c)[1]), "+f"((c)[2]), "+f"((c)[3]) \
                 : "r"((a)[0]), "r"((a)[1]), "r"((a)[2]), "r"((a)[3]), \
                   "r"((b)[0]), "r"((b)[1]))

__device__ __forceinline__ void ld_tile(const float* __restrict__ base, int K, int k0,
                                        int tid, float4 v[4]) {
#pragma unroll
    for (int i = 0; i < 4; i++) {
        int q = tid + i * 256;
        int r = q >> 3, c = q & 7;
        v[i] = *(const float4*)(base + (size_t)r * K + k0 + c * 4);
    }
}

__device__ __forceinline__ void st_tile(char* hi, char* lo, int tid, const float4 v[4]) {
#pragma unroll
    for (int i = 0; i < 4; i++) {
        int q = tid + i * 256;
        int r = q >> 3, c = q & 7;
        float f[4] = {v[i].x, v[i].y, v[i].z, v[i].w};
        uint32_t hw[2], lw[2];
#pragma unroll
        for (int j = 0; j < 2; j++) {
            __nv_bfloat16 h0 = __float2bfloat16_rn(f[2 * j]);
            __nv_bfloat16 h1 = __float2bfloat16_rn(f[2 * j + 1]);
            __nv_bfloat162 hp; hp.x = h0; hp.y = h1;
            __nv_bfloat162 lp;
            lp.x = __float2bfloat16_rn(f[2 * j] - __bfloat162float(h0));
            lp.y = __float2bfloat16_rn(f[2 * j + 1] - __bfloat162float(h1));
            hw[j] = *(uint32_t*)&hp;
            lw[j] = *(uint32_t*)&lp;
        }
        uint32_t off = (uint32_t)r * ROWB + c * 8;
        *(uint2*)(hi + off) = make_uint2(hw[0], hw[1]);
        *(uint2*)(lo + off) = make_uint2(lw[0], lw[1]);
    }
}

template <int EPI>
__global__ void __launch_bounds__(256, 1) mma_gemm(int M, int N, int K,
                                                   const float* __restrict__ A,
                                                   const float* __restrict__ B,
                                                   float* __restrict__ C,
                                                   const float* __restrict__ bias,
                                                   const float* __restrict__ res) {
    extern __shared__ char smem[];
    const uint32_t sb = smem_u32(smem);
    const int tid = threadIdx.x;
    const int wid = tid >> 5;
    const int lane = tid & 31;
    const int warp_m = wid >> 2;
    const int warp_n = wid & 3;

    const float* Ab = A + (size_t)(blockIdx.y * 128) * K;
    const float* Bb = B + (size_t)(blockIdx.x * 128) * K;

    float acc[4][4][4];
#pragma unroll
    for (int i = 0; i < 4; i++)
#pragma unroll
        for (int j = 0; j < 4; j++)
#pragma unroll
            for (int u = 0; u < 4; u++) acc[i][j][u] = 0.f;

    const int nc = K >> 5;

    // A: x4 ldmatrix -> {rows0-7/k0, rows8-15/k0, rows0-7/k8, rows8-15/k8}
    const int a_lrow = lane & 15;
    const int a_lbyte = (lane >> 4) * 16;
    // B: x4 ldmatrix -> {n0-7/k0, n0-7/k8, n8-15/k0, n8-15/k8}
    const int bj = lane >> 3;
    const int b_lrow = (bj >> 1) * 8 + (lane & 7);
    const int b_lbyte = (bj & 1) * 16;

    float4 va[4], vb[4];
    ld_tile(Ab, K, 0, tid, va);
    ld_tile(Bb, K, 0, tid, vb);
    st_tile(smem, smem + OFF_ALO, tid, va);
    st_tile(smem + OFF_BHI, smem + OFF_BLO, tid, vb);
    __syncthreads();

    for (int c = 0; c < nc; c++) {
        const int buf = c & 1;
        const uint32_t st = sb + buf * STAGE_BYTES;

        if (c + 1 < nc) {
            ld_tile(Ab, K, (c + 1) << 5, tid, va);
            ld_tile(Bb, K, (c + 1) << 5, tid, vb);
        }

#pragma unroll
        for (int ks = 0; ks < 2; ks++) {
            uint32_t ah[4][4], al[4][4];
#pragma unroll
            for (int mf = 0; mf < 4; mf++) {
                const uint32_t row = warp_m * 64 + mf * 16 + a_lrow;
                const uint32_t addr = st + row * ROWB + ks * 32 + a_lbyte;
                LDSM4(ah[mf], addr);
                LDSM4(al[mf], addr + OFF_ALO);
            }
            uint32_t bh[4][2], bl[4][2];
#pragma unroll
            for (int nf2 = 0; nf2 < 2; nf2++) {
                const uint32_t row = warp_n * 32 + nf2 * 16 + b_lrow;
                const uint32_t addr = st + OFF_BHI + row * ROWB + ks * 32 + b_lbyte;
                uint32_t r[4];
                LDSM4(r, addr);                       // non-trans: k contiguous in regs
                bh[nf2 * 2][0] = r[0]; bh[nf2 * 2][1] = r[1];
                bh[nf2 * 2 + 1][0] = r[2]; bh[nf2 * 2 + 1][1] = r[3];
                LDSM4(r, addr + TILEB);
                bl[nf2 * 2][0] = r[0]; bl[nf2 * 2][1] = r[1];
                bl[nf2 * 2 + 1][0] = r[2]; bl[nf2 * 2 + 1][1] = r[3];
            }
#pragma unroll
            for (int mf = 0; mf < 4; mf++)
#pragma unroll
                for (int nf = 0; nf < 4; nf++) {
                    MMA_BF16(acc[mf][nf], ah[mf], bh[nf]);
                    MMA_BF16(acc[mf][nf], ah[mf], bl[nf]);
                    MMA_BF16(acc[mf][nf], al[mf], bh[nf]);
                }
        }

        if (c + 1 < nc) {
            char* nst = smem + (buf ^ 1) * STAGE_BYTES;
            st_tile(nst, nst + OFF_ALO, tid, va);
            st_tile(nst + OFF_BHI, nst + OFF_BLO, tid, vb);
        }
        __syncthreads();
    }

    const int rbase = blockIdx.y * 128 + warp_m * 64 + (lane >> 2);
    const int cbase = blockIdx.x * 128 + warp_n * 32 + (lane & 3) * 2;
#pragma unroll
    for (int mf = 0; mf < 4; mf++) {
#pragma unroll
        for (int h = 0; h < 2; h++) {
            const int row_g = rbase + mf * 16 + h * 8;
            float* Crow = C + (size_t)row_g * N;
            const float* Rrow = (EPI == 1 || EPI == 3) ? res + (size_t)row_g * N : nullptr;
#pragma unroll
            for (int nf = 0; nf < 4; nf++) {
                const int col_g = cbase + nf * 8;
                float t0 = acc[mf][nf][2 * h];
                float t1 = acc[mf][nf][2 * h + 1];
                if (EPI == 2 || EPI == 3) { t0 += bias[col_g]; t1 += bias[col_g + 1]; }
                if (EPI == 2) {
                    t0 = 0.5f * t0 * (1.f + erff(t0 * 0.70710678118654752f));
                    t1 = 0.5f * t1 * (1.f + erff(t1 * 0.70710678118654752f));
                }
                if (EPI == 1 || EPI == 3) { t0 += Rrow[col_g]; t1 += Rrow[col_g + 1]; }
                float2 p; p.x = t0; p.y = t1;
                *(float2*)(Crow + col_g) = p;
            }
        }
    }
}

// ---------------- Flash attention (fp32, causal) ----------------
__global__ void __launch_bounds__(128) attn_kernel() {
    const int tid = threadIdx.x;
    const int q0 = blockIdx.x * 128;
    const int hh = blockIdx.y;
    const int bb = blockIdx.z;
    const int s = q0 + tid;

    __shared__ float4 Ks[64 * 16];
    __shared__ float4 Vs[64 * 16];

    float qreg[64];
    {
        const float* qrow = g_qkv + (size_t)(bb * S_ + s) * (3 * D_) + hh * DH_;
#pragma unroll
        for (int i = 0; i < 16; i++) {
            float4 t = *(const float4*)(qrow + i * 4);
            qreg[i * 4 + 0] = t.x; qreg[i * 4 + 1] = t.y;
            qreg[i * 4 + 2] = t.z; qreg[i * 4 + 3] = t.w;
        }
    }

    float acc[64];
#pragma unroll
    for (int d = 0; d < 64; d++) acc[d] = 0.f;
    float m = -INFINITY, l = 0.f;

    const int ntiles = (q0 + 128) / 64;
    for (int t0 = 0; t0 < ntiles; t0++) {
        const int k0 = t0 * 64;
        __syncthreads();
        {
            const float* Kbase = g_qkv + (size_t)(bb * S_ + k0) * (3 * D_) + D_ + hh * DH_;
            const float* Vbase = Kbase + D_;
#pragma unroll
            for (int i = 0; i < 8; i++) {
                int f = tid + i * 128;
                int r = f >> 4, c = f & 15;
                Ks[f] = *(const float4*)(Kbase + (size_t)r * (3 * D_) + c * 4);
                Vs[f] = *(const float4*)(Vbase + (size_t)r * (3 * D_) + c * 4);
            }
        }
        __syncthreads();

        for (int jc = 0; jc < 4; jc++) {
            float sc[16];
#pragma unroll
            for (int jj = 0; jj < 16; jj++) {
                const int j = jc * 16 + jj;
                float sum = 0.f;
#pragma unroll
                for (int d4 = 0; d4 < 16; d4++) {
                    float4 k4 = Ks[j * 16 + d4];
                    sum += qreg[d4 * 4 + 0] * k4.x;
                    sum += qreg[d4 * 4 + 1] * k4.y;
                    sum += qreg[d4 * 4 + 2] * k4.z;
                    sum += qreg[d4 * 4 + 3] * k4.w;
                }
                sc[jj] = (k0 + j <= s) ? sum * 0.125f : -INFINITY;
            }
            float mn = m;
#pragma unroll
            for (int jj = 0; jj < 16; jj++) mn = fmaxf(mn, sc[jj]);
            const float corr = __expf(m - mn);
            float p[16];
            float psum = 0.f;
#pragma unroll
            for (int jj = 0; jj < 16; jj++) {
                p[jj] = __expf(sc[jj] - mn);
                psum += p[jj];
            }
            l = l * corr + psum;
            m = mn;
#pragma unroll
            for (int d = 0; d < 64; d++) acc[d] *= corr;
#pragma unroll
            for (int jj = 0; jj < 16; jj++) {
                const float pv = p[jj];
                const int j = jc * 16 + jj;
#pragma unroll
                for (int d4 = 0; d4 < 16; d4++) {
                    float4 v4 = Vs[j * 16 + d4];
                    acc[d4 * 4 + 0] += pv * v4.x;
                    acc[d4 * 4 + 1] += pv * v4.y;
                    acc[d4 * 4 + 2] += pv * v4.z;
                    acc[d4 * 4 + 3] += pv * v4.w;
                }
            }
        }
    }

    const float inv = 1.f / l;
    float* orow = g_attn + (size_t)(bb * S_ + s) * D_ + hh * DH_;
#pragma unroll
    for (int i = 0; i < 16; i++) {
        float4 o;
        o.x = acc[i * 4 + 0] * inv;
        o.y = acc[i * 4 + 1] * inv;
        o.z = acc[i * 4 + 2] * inv;
        o.w = acc[i * 4 + 3] * inv;
        *(float4*)(orow + i * 4) = o;
    }
}

// ---------------- launch ----------------
extern "C" void kernel_launch(void* const* d_in, const int* in_sizes, int n_in,
                              void* d_out, int out_size) {
    const float* x = (const float*)d_in[0];
    const float* Wqkv = (const float*)d_in[2];
    const float* Wout = (const float*)d_in[3];
    const float* W1 = (const float*)d_in[4];
    const float* b1 = (const float*)d_in[5];
    const float* W2 = (const float*)d_in[6];
    const float* b2 = (const float*)d_in[7];
    const float* gamma1 = (const float*)d_in[8];
    const float* beta1 = (const float*)d_in[9];
    const float* gamma2 = (const float*)d_in[10];
    const float* beta2 = (const float*)d_in[11];
    float* out = (float*)d_out;

    float* h = nullptr; float* qkv = nullptr; float* attn = nullptr;
    float* x1 = nullptr; float* ffn = nullptr;
    cudaGetSymbolAddress((void**)&h, g_h);
    cudaGetSymbolAddress((void**)&qkv, g_qkv);
    cudaGetSymbolAddress((void**)&attn, g_attn);
    cudaGetSymbolAddress((void**)&x1, g_x1);
    cudaGetSymbolAddress((void**)&ffn, g_ffn);

    cudaFuncSetAttribute(mma_gemm<0>, cudaFuncAttributeMaxDynamicSharedMemorySize, GEMM_SMEM);
    cudaFuncSetAttribute(mma_gemm<1>, cudaFuncAttributeMaxDynamicSharedMemorySize, GEMM_SMEM);
    cudaFuncSetAttribute(mma_gemm<2>, cudaFuncAttributeMaxDynamicSharedMemorySize, GEMM_SMEM);
    cudaFuncSetAttribute(mma_gemm<3>, cudaFuncAttributeMaxDynamicSharedMemorySize, GEMM_SMEM);

    // 1) LN1
    ln_kernel<<<NTOK, 256>>>(x, h, gamma1, beta1);
    // 2) QKV projection: [4096,1024] x [3072,1024]^T
    mma_gemm<0><<<dim3(3 * D_ / 128, NTOK / 128), 256, GEMM_SMEM>>>(NTOK, 3 * D_, D_, h, Wqkv, qkv, nullptr, nullptr);
    // 3) causal flash attention
    attn_kernel<<<dim3(S_ / 128, H_, B_), 128>>>();
    // 4) output projection + residual
    mma_gemm<1><<<dim3(D_ / 128, NTOK / 128), 256, GEMM_SMEM>>>(NTOK, D_, D_, attn, Wout, x1, nullptr, x);
    // 5) LN2
    ln_kernel<<<NTOK, 256>>>(x1, h, gamma2, beta2);
    // 6) FFN1 + bias + exact GELU
    mma_gemm<2><<<dim3(F_ / 128, NTOK / 128), 256, GEMM_SMEM>>>(NTOK, F_, D_, h, W1, ffn, b1, nullptr);
    // 7) FFN2 + bias + residual -> out
    mma_gemm<3><<<dim3(D_ / 128, NTOK / 128), 256, GEMM_SMEM>>>(NTOK, D_, F_, ffn, W2, out, b2, x1);
}

// round 7
// speedup vs baseline: 2.9106x; 1.6119x over previous
#include <cuda_runtime.h>
#include <cuda_bf16.h>
#include <math.h>
#include <stdint.h>

#define B_ 2
#define S_ 2048
#define D_ 1024
#define H_ 16
#define DH_ 64
#define F_ 4096
#define NTOK (B_ * S_)   // 4096

// ---------------- scratch (static device globals; no allocation) ----------------
__device__ float g_h[(size_t)NTOK * D_];
__device__ float g_qkv[(size_t)NTOK * 3 * D_];
__device__ float g_attn[(size_t)NTOK * D_];
__device__ float g_x1[(size_t)NTOK * D_];
__device__ float g_ffn[(size_t)NTOK * F_];

__device__ __forceinline__ uint32_t smem_u32(const void* p) {
    uint32_t a;
    asm("{ .reg .u64 t; cvta.to.shared.u64 t, %1; cvt.u32.u64 %0, t; }" : "=r"(a) : "l"(p));
    return a;
}

// ---------------- warp/block reduction helpers ----------------
__device__ __forceinline__ float warp_sum(float v) {
#pragma unroll
    for (int o = 16; o > 0; o >>= 1) v += __shfl_xor_sync(0xffffffffu, v, o);
    return v;
}

// ---------------- LayerNorm ----------------
__global__ void __launch_bounds__(256) ln_kernel(const float* __restrict__ in,
                                                 float* __restrict__ out,
                                                 const float* __restrict__ gamma,
                                                 const float* __restrict__ beta) {
    const int row = blockIdx.x;
    const float* x = in + (size_t)row * D_;
    float* o = out + (size_t)row * D_;
    const int tid = threadIdx.x;
    const int lane = tid & 31;
    const int wid = tid >> 5;

    float v[4];
    float s = 0.f;
#pragma unroll
    for (int i = 0; i < 4; i++) { v[i] = x[tid + i * 256]; s += v[i]; }
    __shared__ float red[8];
    s = warp_sum(s);
    if (lane == 0) red[wid] = s;
    __syncthreads();
    if (tid < 32) {
        float t = (lane < 8) ? red[lane] : 0.f;
        t = warp_sum(t);
        if (lane == 0) red[0] = t;
    }
    __syncthreads();
    const float mean = red[0] * (1.f / D_);
    __syncthreads();

    float q = 0.f;
#pragma unroll
    for (int i = 0; i < 4; i++) { float d = v[i] - mean; q += d * d; }
    q = warp_sum(q);
    if (lane == 0) red[wid] = q;
    __syncthreads();
    if (tid < 32) {
        float t = (lane < 8) ? red[lane] : 0.f;
        t = warp_sum(t);
        if (lane == 0) red[0] = t;
    }
    __syncthreads();
    const float stdv = sqrtf(red[0] * (1.f / D_));
    const float inv = 1.f / (stdv + 1e-6f);

#pragma unroll
    for (int i = 0; i < 4; i++) {
        int c = tid + i * 256;
        o[c] = gamma[c] * ((v[i] - mean) * inv) + beta[c];
    }
}

// ============================================================================
// bf16x3 mma.sync GEMM (unchanged from passing R6 kernel)
// ============================================================================
#define ROWB 80
#define TILEB (128 * ROWB)
#define OFF_ALO (TILEB)
#define OFF_BHI (2 * TILEB)
#define OFF_BLO (3 * TILEB)
#define STAGE_BYTES (4 * TILEB)
#define GEMM_SMEM (2 * STAGE_BYTES)   // 81920

#define LDSM4(r, addr) \
    asm volatile("ldmatrix.sync.aligned.m8n8.x4.shared.b16 {%0,%1,%2,%3}, [%4];" \
                 : "=r"((r)[0]), "=r"((r)[1]), "=r"((r)[2]), "=r"((r)[3]) : "r"(addr))
#define LDSM4T(r, addr) \
    asm volatile("ldmatrix.sync.aligned.m8n8.x4.trans.shared.b16 {%0,%1,%2,%3}, [%4];" \
                 : "=r"((r)[0]), "=r"((r)[1]), "=r"((r)[2]), "=r"((r)[3]) : "r"(addr))
#define MMA_BF16(c, a, b) \
    asm volatile("mma.sync.aligned.m16n8k16.row.col.f32.bf16.bf16.f32 " \
                 "{%0,%1,%2,%3}, {%4,%5,%6,%7}, {%8,%9}, {%0,%1,%2,%3};" \
                 : "+f"((c)[0]), "+f"((c)[1]), "+f"((c)[2]), "+f"((c)[3]) \
                 : "r"((a)[0]), "r"((a)[1]), "r"((a)[2]), "r"((a)[3]), \
                   "r"((b)[0]), "r"((b)[1]))

__device__ __forceinline__ uint32_t packsplit(float x, float y, uint32_t& lo) {
    __nv_bfloat162 hp, lp;
    hp.x = __float2bfloat16_rn(x); hp.y = __float2bfloat16_rn(y);
    lp.x = __float2bfloat16_rn(x - __bfloat162float(hp.x));
    lp.y = __float2bfloat16_rn(y - __bfloat162float(hp.y));
    lo = *(uint32_t*)&lp;
    return *(uint32_t*)&hp;
}

__device__ __forceinline__ void ld_tile(const float* __restrict__ base, int K, int k0,
                                        int tid, float4 v[4]) {
#pragma unroll
    for (int i = 0; i < 4; i++) {
        int q = tid + i * 256;
        int r = q >> 3, c = q & 7;
        v[i] = *(const float4*)(base + (size_t)r * K + k0 + c * 4);
    }
}

__device__ __forceinline__ void st_tile(char* hi, char* lo, int tid, const float4 v[4]) {
#pragma unroll
    for (int i = 0; i < 4; i++) {
        int q = tid + i * 256;
        int r = q >> 3, c = q & 7;
        uint32_t l0, l1;
        uint32_t h0 = packsplit(v[i].x, v[i].y, l0);
        uint32_t h1 = packsplit(v[i].z, v[i].w, l1);
        uint32_t off = (uint32_t)r * ROWB + c * 8;
        *(uint2*)(hi + off) = make_uint2(h0, h1);
        *(uint2*)(lo + off) = make_uint2(l0, l1);
    }
}

template <int EPI>
__global__ void __launch_bounds__(256, 1) mma_gemm(int M, int N, int K,
                                                   const float* __restrict__ A,
                                                   const float* __restrict__ B,
                                                   float* __restrict__ C,
                                                   const float* __restrict__ bias,
                                                   const float* __restrict__ res) {
    extern __shared__ char smem[];
    const uint32_t sb = smem_u32(smem);
    const int tid = threadIdx.x;
    const int wid = tid >> 5;
    const int lane = tid & 31;
    const int warp_m = wid >> 2;
    const int warp_n = wid & 3;

    const float* Ab = A + (size_t)(blockIdx.y * 128) * K;
    const float* Bb = B + (size_t)(blockIdx.x * 128) * K;

    float acc[4][4][4];
#pragma unroll
    for (int i = 0; i < 4; i++)
#pragma unroll
        for (int j = 0; j < 4; j++)
#pragma unroll
            for (int u = 0; u < 4; u++) acc[i][j][u] = 0.f;

    const int nc = K >> 5;

    const int a_lrow = lane & 15;
    const int a_lbyte = (lane >> 4) * 16;
    const int bj = lane >> 3;
    const int b_lrow = (bj >> 1) * 8 + (lane & 7);
    const int b_lbyte = (bj & 1) * 16;

    float4 va[4], vb[4];
    ld_tile(Ab, K, 0, tid, va);
    ld_tile(Bb, K, 0, tid, vb);
    st_tile(smem, smem + OFF_ALO, tid, va);
    st_tile(smem + OFF_BHI, smem + OFF_BLO, tid, vb);
    __syncthreads();

    for (int c = 0; c < nc; c++) {
        const int buf = c & 1;
        const uint32_t st = sb + buf * STAGE_BYTES;

        if (c + 1 < nc) {
            ld_tile(Ab, K, (c + 1) << 5, tid, va);
            ld_tile(Bb, K, (c + 1) << 5, tid, vb);
        }

#pragma unroll
        for (int ks = 0; ks < 2; ks++) {
            uint32_t ah[4][4], al[4][4];
#pragma unroll
            for (int mf = 0; mf < 4; mf++) {
                const uint32_t row = warp_m * 64 + mf * 16 + a_lrow;
                const uint32_t addr = st + row * ROWB + ks * 32 + a_lbyte;
                LDSM4(ah[mf], addr);
                LDSM4(al[mf], addr + OFF_ALO);
            }
            uint32_t bh[4][2], bl[4][2];
#pragma unroll
            for (int nf2 = 0; nf2 < 2; nf2++) {
                const uint32_t row = warp_n * 32 + nf2 * 16 + b_lrow;
                const uint32_t addr = st + OFF_BHI + row * ROWB + ks * 32 + b_lbyte;
                uint32_t r[4];
                LDSM4(r, addr);
                bh[nf2 * 2][0] = r[0]; bh[nf2 * 2][1] = r[1];
                bh[nf2 * 2 + 1][0] = r[2]; bh[nf2 * 2 + 1][1] = r[3];
                LDSM4(r, addr + TILEB);
                bl[nf2 * 2][0] = r[0]; bl[nf2 * 2][1] = r[1];
                bl[nf2 * 2 + 1][0] = r[2]; bl[nf2 * 2 + 1][1] = r[3];
            }
#pragma unroll
            for (int mf = 0; mf < 4; mf++)
#pragma unroll
                for (int nf = 0; nf < 4; nf++) {
                    MMA_BF16(acc[mf][nf], ah[mf], bh[nf]);
                    MMA_BF16(acc[mf][nf], ah[mf], bl[nf]);
                    MMA_BF16(acc[mf][nf], al[mf], bh[nf]);
                }
        }

        if (c + 1 < nc) {
            char* nst = smem + (buf ^ 1) * STAGE_BYTES;
            st_tile(nst, nst + OFF_ALO, tid, va);
            st_tile(nst + OFF_BHI, nst + OFF_BLO, tid, vb);
        }
        __syncthreads();
    }

    const int rbase = blockIdx.y * 128 + warp_m * 64 + (lane >> 2);
    const int cbase = blockIdx.x * 128 + warp_n * 32 + (lane & 3) * 2;
#pragma unroll
    for (int mf = 0; mf < 4; mf++) {
#pragma unroll
        for (int h = 0; h < 2; h++) {
            const int row_g = rbase + mf * 16 + h * 8;
            float* Crow = C + (size_t)row_g * N;
            const float* Rrow = (EPI == 1 || EPI == 3) ? res + (size_t)row_g * N : nullptr;
#pragma unroll
            for (int nf = 0; nf < 4; nf++) {
                const int col_g = cbase + nf * 8;
                float t0 = acc[mf][nf][2 * h];
                float t1 = acc[mf][nf][2 * h + 1];
                if (EPI == 2 || EPI == 3) { t0 += bias[col_g]; t1 += bias[col_g + 1]; }
                if (EPI == 2) {
                    t0 = 0.5f * t0 * (1.f + erff(t0 * 0.70710678118654752f));
                    t1 = 0.5f * t1 * (1.f + erff(t1 * 0.70710678118654752f));
                }
                if (EPI == 1 || EPI == 3) { t0 += Rrow[col_g]; t1 += Rrow[col_g + 1]; }
                float2 p; p.x = t0; p.y = t1;
                *(float2*)(Crow + col_g) = p;
            }
        }
    }
}

// ============================================================================
// MMA flash attention (bf16x3, causal). 128 threads = 4 warps, warp = 32 q-rows.
// SMEM: Q hi/lo (128x64), K hi/lo (64x64), V hi/lo (64x64); 144B row pitch
// (144 mod 128 = 16 -> 8 ldmatrix rows hit distinct bank groups).
// ============================================================================
#define APITCH 144
#define AT_QH 0
#define AT_QL 18432
#define AT_KH 36864
#define AT_KL 46080
#define AT_VH 55296
#define AT_VL 64512
#define AT_SMEM 73728

__device__ __forceinline__ void cvt_store(char* hi, char* lo, uint32_t off, float4 f) {
    uint32_t l0, l1;
    uint32_t h0 = packsplit(f.x, f.y, l0);
    uint32_t h1 = packsplit(f.z, f.w, l1);
    *(uint2*)(hi + off) = make_uint2(h0, h1);
    *(uint2*)(lo + off) = make_uint2(l0, l1);
}

__global__ void __launch_bounds__(128) attn_mma() {
    extern __shared__ char smem[];
    const uint32_t sb = smem_u32(smem);
    const int tid = threadIdx.x;
    const int lane = tid & 31;
    const int wid = tid >> 5;
    const int q0 = blockIdx.x * 128;
    const int hh = blockIdx.y;
    const int bb = blockIdx.z;

    // load Q tile (128 x 64) -> hi/lo
#pragma unroll
    for (int i = 0; i < 16; i++) {
        int idx = tid + i * 128;
        int r = idx >> 4, c4 = idx & 15;
        float4 f = *(const float4*)(g_qkv + (size_t)(bb * S_ + q0 + r) * (3 * D_) + hh * DH_ + c4 * 4);
        cvt_store(smem + AT_QH, smem + AT_QL, (uint32_t)r * APITCH + c4 * 8, f);
    }

    float O[2][8][4];
#pragma unroll
    for (int a = 0; a < 2; a++)
#pragma unroll
        for (int b = 0; b < 8; b++)
#pragma unroll
            for (int u = 0; u < 4; u++) O[a][b][u] = 0.f;
    float mrow[2][2] = {{-INFINITY, -INFINITY}, {-INFINITY, -INFINITY}};
    float lrow[2][2] = {{0.f, 0.f}, {0.f, 0.f}};

    const int a_lrow = lane & 15;
    const int a_lbyte = (lane >> 4) * 16;
    const int bj = lane >> 3;
    const int b_lrow = (bj >> 1) * 8 + (lane & 7);
    const int b_lbyte = (bj & 1) * 16;
    const int v_key = (bj & 1) * 8 + (lane & 7);   // trans: mat&1 -> key+8
    const int v_d = (bj >> 1) * 8;                 // trans: mat>>1 -> d+8

    const int ntiles = blockIdx.x * 2 + 2;
    const int rowmax_warp = q0 + wid * 32 + 31;

    for (int t0 = 0; t0 < ntiles; t0++) {
        const int k0 = t0 * 64;
        __syncthreads();
#pragma unroll
        for (int i = 0; i < 8; i++) {
            int idx = tid + i * 128;
            int r = idx >> 4, c4 = idx & 15;
            const float* kb = g_qkv + (size_t)(bb * S_ + k0 + r) * (3 * D_) + D_ + hh * DH_ + c4 * 4;
            cvt_store(smem + AT_KH, smem + AT_KL, (uint32_t)r * APITCH + c4 * 8, *(const float4*)kb);
            cvt_store(smem + AT_VH, smem + AT_VL, (uint32_t)r * APITCH + c4 * 8, *(const float4*)(kb + D_));
        }
        __syncthreads();
        if (k0 > rowmax_warp) continue;   // whole warp masked this tile

        // ---- S = Q K^T (bf16x3) ----
        float S[2][8][4] = {};
#pragma unroll
        for (int kf = 0; kf < 4; kf++) {
            uint32_t qh[2][4], ql[2][4];
#pragma unroll
            for (int mf = 0; mf < 2; mf++) {
                const uint32_t addr = sb + AT_QH + (uint32_t)(wid * 32 + mf * 16 + a_lrow) * APITCH + kf * 32 + a_lbyte;
                LDSM4(qh[mf], addr);
                LDSM4(ql[mf], addr + (AT_QL - AT_QH));
            }
            uint32_t kh[8][2], kl[8][2];
#pragma unroll
            for (int p = 0; p < 4; p++) {
                const uint32_t addr = sb + AT_KH + (uint32_t)(p * 16 + b_lrow) * APITCH + kf * 32 + b_lbyte;
                uint32_t r4[4];
                LDSM4(r4, addr);
                kh[2 * p][0] = r4[0]; kh[2 * p][1] = r4[1];
                kh[2 * p + 1][0] = r4[2]; kh[2 * p + 1][1] = r4[3];
                LDSM4(r4, addr + (AT_KL - AT_KH));
                kl[2 * p][0] = r4[0]; kl[2 * p][1] = r4[1];
                kl[2 * p + 1][0] = r4[2]; kl[2 * p + 1][1] = r4[3];
            }
#pragma unroll
            for (int mf = 0; mf < 2; mf++)
#pragma unroll
                for (int nf = 0; nf < 8; nf++) {
                    MMA_BF16(S[mf][nf], qh[mf], kh[nf]);
                    MMA_BF16(S[mf][nf], qh[mf], kl[nf]);
                    MMA_BF16(S[mf][nf], ql[mf], kh[nf]);
                }
        }

        // ---- online softmax (per row; quad shares a row) ----
#pragma unroll
        for (int mf = 0; mf < 2; mf++)
#pragma unroll
            for (int h = 0; h < 2; h++) {
                const int rowg = q0 + wid * 32 + mf * 16 + (lane >> 2) + h * 8;
                float tmax = -INFINITY;
#pragma unroll
                for (int nf = 0; nf < 8; nf++) {
                    const int colg = k0 + nf * 8 + (lane & 3) * 2;
                    float s0 = S[mf][nf][2 * h] * 0.125f;
                    float s1 = S[mf][nf][2 * h + 1] * 0.125f;
                    if (colg > rowg) s0 = -INFINITY;
                    if (colg + 1 > rowg) s1 = -INFINITY;
                    S[mf][nf][2 * h] = s0;
                    S[mf][nf][2 * h + 1] = s1;
                    tmax = fmaxf(tmax, fmaxf(s0, s1));
                }
                tmax = fmaxf(tmax, __shfl_xor_sync(0xffffffffu, tmax, 1));
                tmax = fmaxf(tmax, __shfl_xor_sync(0xffffffffu, tmax, 2));
                const float mn = fmaxf(mrow[mf][h], tmax);
                const float corr = __expf(mrow[mf][h] - mn);
                mrow[mf][h] = mn;
                float ps = 0.f;
#pragma unroll
                for (int nf = 0; nf < 8; nf++) {
                    float p0 = __expf(S[mf][nf][2 * h] - mn);
                    float p1 = __expf(S[mf][nf][2 * h + 1] - mn);
                    S[mf][nf][2 * h] = p0;
                    S[mf][nf][2 * h + 1] = p1;
                    ps += p0 + p1;
                }
                ps += __shfl_xor_sync(0xffffffffu, ps, 1);
                ps += __shfl_xor_sync(0xffffffffu, ps, 2);
                lrow[mf][h] = lrow[mf][h] * corr + ps;
#pragma unroll
                for (int nd = 0; nd < 8; nd++) {
                    O[mf][nd][2 * h] *= corr;
                    O[mf][nd][2 * h + 1] *= corr;
                }
            }

        // ---- O += P V (P split in regs, V hi/lo via ldmatrix.trans) ----
#pragma unroll
        for (int kf = 0; kf < 4; kf++) {
            uint32_t ph[2][4], pl[2][4];
#pragma unroll
            for (int mf = 0; mf < 2; mf++) {
                ph[mf][0] = packsplit(S[mf][2 * kf][0], S[mf][2 * kf][1], pl[mf][0]);
                ph[mf][1] = packsplit(S[mf][2 * kf][2], S[mf][2 * kf][3], pl[mf][1]);
                ph[mf][2] = packsplit(S[mf][2 * kf + 1][0], S[mf][2 * kf + 1][1], pl[mf][2]);
                ph[mf][3] = packsplit(S[mf][2 * kf + 1][2], S[mf][2 * kf + 1][3], pl[mf][3]);
            }
            uint32_t vh[8][2], vl[8][2];
#pragma unroll
            for (int db = 0; db < 4; db++) {
                const uint32_t addr = sb + AT_VH + (uint32_t)(kf * 16 + v_key) * APITCH + (db * 16 + v_d) * 2;
                uint32_t r4[4];
                LDSM4T(r4, addr);
                vh[2 * db][0] = r4[0]; vh[2 * db][1] = r4[1];
                vh[2 * db + 1][0] = r4[2]; vh[2 * db + 1][1] = r4[3];
                LDSM4T(r4, addr + (AT_VL - AT_VH));
                vl[2 * db][0] = r4[0]; vl[2 * db][1] = r4[1];
                vl[2 * db + 1][0] = r4[2]; vl[2 * db + 1][1] = r4[3];
            }
#pragma unroll
            for (int mf = 0; mf < 2; mf++)
#pragma unroll
                for (int nd = 0; nd < 8; nd++) {
                    MMA_BF16(O[mf][nd], ph[mf], vh[nd]);
                    MMA_BF16(O[mf][nd], ph[mf], vl[nd]);
                    MMA_BF16(O[mf][nd], pl[mf], vh[nd]);
                }
        }
    }

    // ---- epilogue: O /= l ----
#pragma unroll
    for (int mf = 0; mf < 2; mf++)
#pragma unroll
        for (int h = 0; h < 2; h++) {
            const float inv = 1.f / lrow[mf][h];
            const int rowg = q0 + wid * 32 + mf * 16 + (lane >> 2) + h * 8;
            float* orow = g_attn + (size_t)(bb * S_ + rowg) * D_ + hh * DH_;
#pragma unroll
            for (int nd = 0; nd < 8; nd++) {
                const int col = nd * 8 + (lane & 3) * 2;
                float2 p;
                p.x = O[mf][nd][2 * h] * inv;
                p.y = O[mf][nd][2 * h + 1] * inv;
                *(float2*)(orow + col) = p;
            }
        }
}

// ---------------- launch ----------------
extern "C" void kernel_launch(void* const* d_in, const int* in_sizes, int n_in,
                              void* d_out, int out_size) {
    const float* x = (const float*)d_in[0];
    const float* Wqkv = (const float*)d_in[2];
    const float* Wout = (const float*)d_in[3];
    const float* W1 = (const float*)d_in[4];
    const float* b1 = (const float*)d_in[5];
    const float* W2 = (const float*)d_in[6];
    const float* b2 = (const float*)d_in[7];
    const float* gamma1 = (const float*)d_in[8];
    const float* beta1 = (const float*)d_in[9];
    const float* gamma2 = (const float*)d_in[10];
    const float* beta2 = (const float*)d_in[11];
    float* out = (float*)d_out;

    float* h = nullptr; float* qkv = nullptr; float* attn = nullptr;
    float* x1 = nullptr; float* ffn = nullptr;
    cudaGetSymbolAddress((void**)&h, g_h);
    cudaGetSymbolAddress((void**)&qkv, g_qkv);
    cudaGetSymbolAddress((void**)&attn, g_attn);
    cudaGetSymbolAddress((void**)&x1, g_x1);
    cudaGetSymbolAddress((void**)&ffn, g_ffn);

    cudaFuncSetAttribute(mma_gemm<0>, cudaFuncAttributeMaxDynamicSharedMemorySize, GEMM_SMEM);
    cudaFuncSetAttribute(mma_gemm<1>, cudaFuncAttributeMaxDynamicSharedMemorySize, GEMM_SMEM);
    cudaFuncSetAttribute(mma_gemm<2>, cudaFuncAttributeMaxDynamicSharedMemorySize, GEMM_SMEM);
    cudaFuncSetAttribute(mma_gemm<3>, cudaFuncAttributeMaxDynamicSharedMemorySize, GEMM_SMEM);
    cudaFuncSetAttribute(attn_mma, cudaFuncAttributeMaxDynamicSharedMemorySize, AT_SMEM);

    // 1) LN1
    ln_kernel<<<NTOK, 256>>>(x, h, gamma1, beta1);
    // 2) QKV projection
    mma_gemm<0><<<dim3(3 * D_ / 128, NTOK / 128), 256, GEMM_SMEM>>>(NTOK, 3 * D_, D_, h, Wqkv, qkv, nullptr, nullptr);
    // 3) causal flash attention (tensor-core)
    attn_mma<<<dim3(S_ / 128, H_, B_), 128, AT_SMEM>>>();
    // 4) output projection + residual
    mma_gemm<1><<<dim3(D_ / 128, NTOK / 128), 256, GEMM_SMEM>>>(NTOK, D_, D_, attn, Wout, x1, nullptr, x);
    // 5) LN2
    ln_kernel<<<NTOK, 256>>>(x1, h, gamma2, beta2);
    // 6) FFN1 + bias + exact GELU
    mma_gemm<2><<<dim3(F_ / 128, NTOK / 128), 256, GEMM_SMEM>>>(NTOK, F_, D_, h, W1, ffn, b1, nullptr);
    // 7) FFN2 + bias + residual -> out
    mma_gemm<3><<<dim3(D_ / 128, NTOK / 128), 256, GEMM_SMEM>>>(NTOK, D_, F_, ffn, W2, out, b2, x1);
}